// round 10
// baseline (speedup 1.0000x reference)
#include <cuda_runtime.h>
#include <cuda_bf16.h>
#include <cstdint>

// ---------------------------------------------------------------------------
// NTXent loss, fused:
//   loss = mean_i [ 2 + log( sum_{j!=i} exp(2*cos(i,j) - 2) ) - 2*cos(i,pair(i)) ]
// (fixed LSE shift of 2.0 is exact since sim <= 2; exp args in [-4,0])
// ---------------------------------------------------------------------------

#define N_TOT   8192
#define HALF_N  4096
#define KD      256
#define BM      128
#define BN      128
#define SA      264            // padded SMEM row stride (bf16 elems) -> 528B, ldmatrix conflict-free
#define NBLK_J  32             // j-blocks per jsplit (64 total / 2 splits)
#define SMEM_MAIN (3*BM*SA*2 + 2*128*4)   // A + 2xB (bf16) + reduction scratch

__device__ alignas(16) __nv_bfloat16 g_zn[(size_t)N_TOT * KD]; // normalized z, bf16
__device__ float g_rowsum[2][N_TOT];                           // per-jsplit partial exp-sums
__device__ float g_spair[N_TOT];                               // positive-pair logit per row

// ------------------------------- kernel 1 ----------------------------------
__global__ void normalize_kernel(const float* __restrict__ zi,
                                 const float* __restrict__ zj) {
    const int row = blockIdx.x;
    const int tid = threadIdx.x;            // 256 threads = one row
    const float* src = (row < HALF_N) ? (zi + (size_t)row * KD)
                                      : (zj + (size_t)(row - HALF_N) * KD);
    float v = src[tid];
    float s = v * v;
#pragma unroll
    for (int o = 16; o > 0; o >>= 1) s += __shfl_xor_sync(0xffffffffu, s, o);
    __shared__ float red[8];
    const int warp = tid >> 5, lane = tid & 31;
    if (lane == 0) red[warp] = s;
    __syncthreads();
    if (tid == 0) {
        float t = 0.f;
#pragma unroll
        for (int w = 0; w < 8; ++w) t += red[w];
        red[0] = fmaxf(sqrtf(t), 1e-12f);
    }
    __syncthreads();
    const float inv = 1.0f / red[0];
    g_zn[(size_t)row * KD + tid] = __float2bfloat16(v * inv);
}

// ------------------------------ PTX helpers --------------------------------
__device__ __forceinline__ void ldsm4(unsigned& r0, unsigned& r1, unsigned& r2,
                                      unsigned& r3, unsigned addr) {
    asm volatile("ldmatrix.sync.aligned.m8n8.x4.shared.b16 {%0,%1,%2,%3}, [%4];\n"
                 : "=r"(r0), "=r"(r1), "=r"(r2), "=r"(r3) : "r"(addr));
}
__device__ __forceinline__ void mma16816(float* c, const unsigned* a, const unsigned* b) {
    asm volatile(
        "mma.sync.aligned.m16n8k16.row.col.f32.bf16.bf16.f32 "
        "{%0,%1,%2,%3}, {%4,%5,%6,%7}, {%8,%9}, {%0,%1,%2,%3};\n"
        : "+f"(c[0]), "+f"(c[1]), "+f"(c[2]), "+f"(c[3])
        : "r"(a[0]), "r"(a[1]), "r"(a[2]), "r"(a[3]), "r"(b[0]), "r"(b[1]));
}
__device__ __forceinline__ void cp16(void* dst, const void* src) {
    unsigned s = (unsigned)__cvta_generic_to_shared(dst);
    asm volatile("cp.async.ca.shared.global [%0], [%1], 16;\n" ::"r"(s), "l"(src));
}

// ------------------------------- kernel 2 ----------------------------------
// grid (64, 2): blockIdx.x = 128-row block, blockIdx.y = half of the j-range.
// 8 warps: (wm 0..3, wn 0..1), warp tile 32x64, fragments 16x8 -> 2x8 mma tiles.
__global__ void __launch_bounds__(256, 1) ntxent_main() {
    extern __shared__ __nv_bfloat16 sm[];
    __nv_bfloat16* sA = sm;                              // [128][264]
    __nv_bfloat16* sBbuf[2] = { sm + BM * SA, sm + 2 * BM * SA };
    float* sRed = (float*)(sm + 3 * BM * SA);            // [2][128]

    const int tid  = threadIdx.x;
    const int lane = tid & 31;
    const int warp = tid >> 5;
    const int wm = warp >> 1, wn = warp & 1;
    const int bx = blockIdx.x;
    const int jsplit = blockIdx.y;
    const int row0 = bx * BM;
    const int jb0  = jsplit * NBLK_J;
    const int pair_jb = (bx < 32) ? bx + 32 : bx - 32;   // j-block holding column i±4096

    // Prefetch first B tile (async), then load A tile (plain, resident all 32 blocks).
    {
        const int jb = jb0;
#pragma unroll
        for (int it = 0; it < 16; ++it) {
            int idx = it * 256 + tid;
            int r = idx >> 5, ch = idx & 31;             // 128 rows x 32 chunks of 16B
            cp16(sBbuf[0] + r * SA + ch * 8,
                 g_zn + (size_t)(jb * BN + r) * KD + ch * 8);
        }
        asm volatile("cp.async.commit_group;\n");
    }
#pragma unroll
    for (int it = 0; it < 16; ++it) {
        int idx = it * 256 + tid;
        int r = idx >> 5, ch = idx & 31;
        *(uint4*)(sA + r * SA + ch * 8) =
            *(const uint4*)(g_zn + (size_t)(row0 + r) * KD + ch * 8);
    }

    const unsigned aBase  = (unsigned)__cvta_generic_to_shared(sA);
    const unsigned bBase0 = (unsigned)__cvta_generic_to_shared(sBbuf[0]);
    const unsigned bBase1 = (unsigned)__cvta_generic_to_shared(sBbuf[1]);

    // ldmatrix per-lane address components (element units; *2 for bytes at use).
    const int aRowOff = (wm * 32 + (lane & 15)) * SA + ((lane >> 4) & 1) * 8;
    const int bRowOff = (wn * 64 + ((lane >> 4) & 1) * 8 + (lane & 7)) * SA
                        + ((lane >> 3) & 1) * 8;

    float rsum[2][2] = {{0.f, 0.f}, {0.f, 0.f}};         // rows wm*32 + mt*16 + h*8 + lane/4

    for (int t = 0; t < NBLK_J; ++t) {
        if (t + 1 < NBLK_J) {                            // prefetch next B tile
            __nv_bfloat16* nb = sBbuf[(t + 1) & 1];
            const int jb = jb0 + t + 1;
#pragma unroll
            for (int it = 0; it < 16; ++it) {
                int idx = it * 256 + tid;
                int r = idx >> 5, ch = idx & 31;
                cp16(nb + r * SA + ch * 8,
                     g_zn + (size_t)(jb * BN + r) * KD + ch * 8);
            }
            asm volatile("cp.async.commit_group;\n");
            asm volatile("cp.async.wait_group 1;\n");
        } else {
            asm volatile("cp.async.wait_group 0;\n");
        }
        __syncthreads();

        const unsigned bBase = (t & 1) ? bBase1 : bBase0;
        float c[2][8][4];
#pragma unroll
        for (int mt = 0; mt < 2; ++mt)
#pragma unroll
            for (int nt = 0; nt < 8; ++nt)
#pragma unroll
                for (int r = 0; r < 4; ++r) c[mt][nt][r] = 0.f;

#pragma unroll
        for (int ks = 0; ks < 16; ++ks) {
            unsigned a[2][4], b[8][2];
            ldsm4(a[0][0], a[0][1], a[0][2], a[0][3],
                  aBase + (unsigned)((aRowOff + ks * 16) * 2));
            ldsm4(a[1][0], a[1][1], a[1][2], a[1][3],
                  aBase + (unsigned)((aRowOff + 16 * SA + ks * 16) * 2));
#pragma unroll
            for (int np = 0; np < 4; ++np) {
                ldsm4(b[2 * np][0], b[2 * np][1], b[2 * np + 1][0], b[2 * np + 1][1],
                      bBase + (unsigned)((bRowOff + np * 16 * SA + ks * 16) * 2));
            }
#pragma unroll
            for (int mt = 0; mt < 2; ++mt)
#pragma unroll
                for (int nt = 0; nt < 8; ++nt)
                    mma16816(c[mt][nt], a[mt], b[nt]);
        }

        // Fused epilogue: exp-sum (diag excluded), positive-pair capture.
        const int jb = jb0 + t;
        const bool isDiag = (jb == bx);
        const bool isPair = (jb == pair_jb);
#pragma unroll
        for (int mt = 0; mt < 2; ++mt) {
#pragma unroll
            for (int nt = 0; nt < 8; ++nt) {
#pragma unroll
                for (int r = 0; r < 4; ++r) {
                    int i = row0 + wm * 32 + mt * 16 + ((r >> 1) << 3) + (lane >> 2);
                    int j = jb * BN + wn * 64 + nt * 8 + ((lane & 3) << 1) + (r & 1);
                    float s = c[mt][nt][r] * 2.0f;        // sim = dot / 0.5
                    float e = __expf(s - 2.0f);
                    if (isDiag && (i == j)) e = 0.f;
                    if (isPair) {
                        int pj = (i < HALF_N) ? (i + HALF_N) : (i - HALF_N);
                        if (j == pj) g_spair[i] = s;
                    }
                    rsum[mt][r >> 1] += e;
                }
            }
        }
        __syncthreads();   // protect buffer about to be overwritten by next prefetch
    }

    // Row reduction: sum over lane%4 (column quads), then over the two wn warps.
#pragma unroll
    for (int mt = 0; mt < 2; ++mt) {
#pragma unroll
        for (int h = 0; h < 2; ++h) {
            float v = rsum[mt][h];
            v += __shfl_xor_sync(0xffffffffu, v, 1);
            v += __shfl_xor_sync(0xffffffffu, v, 2);
            if ((lane & 3) == 0) {
                int lr = wm * 32 + mt * 16 + h * 8 + (lane >> 2);
                sRed[wn * 128 + lr] = v;
            }
        }
    }
    __syncthreads();
    if (tid < 128)
        g_rowsum[jsplit][row0 + tid] = sRed[tid] + sRed[128 + tid];
}

// ------------------------------- kernel 3 ----------------------------------
__global__ void reduce_kernel(float* __restrict__ out) {
    const int tid = threadIdx.x;
    float acc = 0.f;
    for (int i = tid; i < N_TOT; i += 256) {
        float rs = g_rowsum[0][i] + g_rowsum[1][i];
        acc += 2.0f + logf(rs) - g_spair[i];
    }
#pragma unroll
    for (int o = 16; o > 0; o >>= 1) acc += __shfl_xor_sync(0xffffffffu, acc, o);
    __shared__ float red[8];
    const int warp = tid >> 5, lane = tid & 31;
    if (lane == 0) red[warp] = acc;
    __syncthreads();
    if (tid == 0) {
        float t = 0.f;
#pragma unroll
        for (int w = 0; w < 8; ++w) t += red[w];
        out[0] = t / (float)N_TOT;
    }
}

// ------------------------------- launcher ----------------------------------
extern "C" void kernel_launch(void* const* d_in, const int* in_sizes, int n_in,
                              void* d_out, int out_size) {
    const float* zi = (const float*)d_in[0];
    const float* zj = (const float*)d_in[1];
    float* out = (float*)d_out;

    cudaFuncSetAttribute(ntxent_main,
                         cudaFuncAttributeMaxDynamicSharedMemorySize, SMEM_MAIN);

    normalize_kernel<<<N_TOT, 256>>>(zi, zj);
    dim3 grid(N_TOT / BM, 2);                // (64, 2) = 128 CTAs, one wave
    ntxent_main<<<grid, 256, SMEM_MAIN>>>();
    reduce_kernel<<<1, 256>>>(out);
}